// round 4
// baseline (speedup 1.0000x reference)
#include <cuda_runtime.h>

#define NN 100000
#define NE 1600000
#define F_IN 64
#define F_HID 64
#define F_OUT 32

#define SCAN_BLK 1024
#define SCAN_NBLK ((NN + SCAN_BLK - 1) / SCAN_BLK)   // 98

// ---- scratch (device globals; no allocation allowed) ----
__device__ float g_h1  [NN * F_HID];   // x@W1 (unscaled), gathered by SpMM1
__device__ float g_agg1[NN * F_HID];
__device__ float g_h2  [NN * F_OUT];
__device__ float g_outnorm[NN];
__device__ float g_innorm [NN];
__device__ int   g_degs[NN];
__device__ int   g_degd[NN];
__device__ int   g_rowptr[NN + 1];
__device__ int   g_cursor[NN];
__device__ int   g_csr_src[NE];
__device__ int   g_blocksums[SCAN_NBLK];

// ---- zero degree counters ----
__global__ void k_zero() {
    int i = blockIdx.x * blockDim.x + threadIdx.x;
    if (i < NN) { g_degs[i] = 0; g_degd[i] = 0; }
}

// ---- degrees ----
__global__ void k_deg(const int* __restrict__ src, const int* __restrict__ dst) {
    int e = blockIdx.x * blockDim.x + threadIdx.x;
    if (e < NE) {
        atomicAdd(&g_degs[src[e]], 1);
        atomicAdd(&g_degd[dst[e]], 1);
    }
}

// ---- scan stage 1: per-block exclusive scan of dst-degrees ----
__global__ __launch_bounds__(256) void k_scan1() {
    __shared__ int wsum[8];
    int t = threadIdx.x, b = blockIdx.x;
    int base = b * SCAN_BLK + t * 4;
    int v0 = 0, v1 = 0, v2 = 0, v3 = 0;
    if (base + 0 < NN) v0 = g_degd[base + 0];
    if (base + 1 < NN) v1 = g_degd[base + 1];
    if (base + 2 < NN) v2 = g_degd[base + 2];
    if (base + 3 < NN) v3 = g_degd[base + 3];
    int sum = v0 + v1 + v2 + v3;

    int lane = t & 31, wid = t >> 5;
    int x = sum;
    #pragma unroll
    for (int o = 1; o < 32; o <<= 1) {
        int y = __shfl_up_sync(0xffffffffu, x, o);
        if (lane >= o) x += y;
    }
    if (lane == 31) wsum[wid] = x;
    __syncthreads();
    if (wid == 0 && lane < 8) {
        int w = wsum[lane];
        #pragma unroll
        for (int o = 1; o < 8; o <<= 1) {
            int y = __shfl_up_sync(0x000000ffu, w, o);
            if (lane >= o) w += y;
        }
        wsum[lane] = w;
    }
    __syncthreads();
    int incl = x + (wid > 0 ? wsum[wid - 1] : 0);
    int excl = incl - sum;

    if (base + 0 < NN) g_rowptr[base + 0] = excl;
    if (base + 1 < NN) g_rowptr[base + 1] = excl + v0;
    if (base + 2 < NN) g_rowptr[base + 2] = excl + v0 + v1;
    if (base + 3 < NN) g_rowptr[base + 3] = excl + v0 + v1 + v2;
    if (t == 255) g_blocksums[b] = incl;
}

// ---- scan stage 2: exclusive scan of the 98 block sums ----
__global__ __launch_bounds__(128) void k_scan2() {
    __shared__ int wsum[4];
    int t = threadIdx.x;
    int v = (t < SCAN_NBLK) ? g_blocksums[t] : 0;
    int lane = t & 31, wid = t >> 5;
    int x = v;
    #pragma unroll
    for (int o = 1; o < 32; o <<= 1) {
        int y = __shfl_up_sync(0xffffffffu, x, o);
        if (lane >= o) x += y;
    }
    if (lane == 31) wsum[wid] = x;
    __syncthreads();
    if (wid == 0 && lane < 4) {
        int w = wsum[lane];
        #pragma unroll
        for (int o = 1; o < 4; o <<= 1) {
            int y = __shfl_up_sync(0x0000000fu, w, o);
            if (lane >= o) w += y;
        }
        wsum[lane] = w;
    }
    __syncthreads();
    int incl = x + (wid > 0 ? wsum[wid - 1] : 0);
    if (t < SCAN_NBLK) g_blocksums[t] = incl - v;
}

// ---- scan stage 3 + norms ----
__global__ void k_scan3norm() {
    int i = blockIdx.x * blockDim.x + threadIdx.x;
    if (i < NN) {
        int r = g_rowptr[i] + g_blocksums[i >> 10];
        g_rowptr[i] = r;
        g_cursor[i] = r;
        int ds = g_degs[i]; if (ds < 1) ds = 1;
        int dd = g_degd[i]; if (dd < 1) dd = 1;
        g_outnorm[i] = rsqrtf((float)ds);
        g_innorm[i]  = rsqrtf((float)dd);
    }
    if (i == 0) g_rowptr[NN] = NE;
}

// ---- bucket: CSR adjacency (src ids grouped by dst) ----
__global__ void k_bucket(const int* __restrict__ src, const int* __restrict__ dst) {
    int e = blockIdx.x * blockDim.x + threadIdx.x;
    if (e < NE) {
        int pos = atomicAdd(&g_cursor[dst[e]], 1);
        g_csr_src[pos] = src[e];
    }
}

// ---- GEMM1: h1 = x @ W1  (no norm scaling — deferred to gather1) ----
__global__ __launch_bounds__(256) void k_gemm1(const float* __restrict__ x,
                                               const float* __restrict__ W1) {
    __shared__ float Ws[64 * 64];
    __shared__ float xs[64][68];
    int tid = threadIdx.x;
    int nb  = blockIdx.x * 64;

    #pragma unroll
    for (int r = 0; r < 4; r++) {
        int idx = tid + r * 256;
        reinterpret_cast<float4*>(Ws)[idx] =
            reinterpret_cast<const float4*>(W1)[idx];
    }
    #pragma unroll
    for (int r = 0; r < 4; r++) {
        int idx = tid + r * 256;
        int n = idx >> 4, k4 = idx & 15;
        int node = nb + n;
        float4 v = make_float4(0.f, 0.f, 0.f, 0.f);
        if (node < NN)
            v = reinterpret_cast<const float4*>(x)[node * 16 + k4];
        xs[k4 * 4 + 0][n] = v.x;
        xs[k4 * 4 + 1][n] = v.y;
        xs[k4 * 4 + 2][n] = v.z;
        xs[k4 * 4 + 3][n] = v.w;
    }
    __syncthreads();

    int tx = tid & 15;
    int ty = tid >> 4;
    float acc[4][4] = {};
    #pragma unroll
    for (int k = 0; k < 64; k++) {
        float4 wv = *reinterpret_cast<const float4*>(&Ws[k * 64 + tx * 4]);
        float4 xv = *reinterpret_cast<const float4*>(&xs[k][ty * 4]);
        float xr[4] = {xv.x, xv.y, xv.z, xv.w};
        float wr[4] = {wv.x, wv.y, wv.z, wv.w};
        #pragma unroll
        for (int i = 0; i < 4; i++)
            #pragma unroll
            for (int j = 0; j < 4; j++)
                acc[i][j] += xr[i] * wr[j];
    }
    #pragma unroll
    for (int i = 0; i < 4; i++) {
        int node = nb + ty * 4 + i;
        if (node < NN) {
            float4 o = make_float4(acc[i][0], acc[i][1], acc[i][2], acc[i][3]);
            reinterpret_cast<float4*>(g_h1)[node * 16 + tx] = o;
        }
    }
}

// ---- gather1: agg1[n] = sum_s h1[s]*outnorm[s].  Half-warp per node, float4. ----
__global__ __launch_bounds__(256) void k_gather1() {
    int gw = (blockIdx.x * 256 + threadIdx.x) >> 5;
    int lane = threadIdx.x & 31;
    int half = lane >> 4, hl = lane & 15;
    int node = gw * 2 + half;
    if (node >= NN) return;
    unsigned hmask = 0xFFFFu << (half * 16);
    int beg = g_rowptr[node], end = g_rowptr[node + 1];

    float4 a0 = make_float4(0.f,0.f,0.f,0.f), a1 = a0, a2 = a0, a3 = a0;
    for (int c = beg; c < end; c += 16) {
        int idx = c + hl;
        int sreg = 0; float snorm = 0.f;
        if (idx < end) { sreg = g_csr_src[idx]; snorm = g_outnorm[sreg]; }
        int n = end - c; if (n > 16) n = 16;
        int j = 0;
        for (; j + 4 <= n; j += 4) {
            int   s0 = __shfl_sync(hmask, sreg,  j + 0, 16);
            int   s1 = __shfl_sync(hmask, sreg,  j + 1, 16);
            int   s2 = __shfl_sync(hmask, sreg,  j + 2, 16);
            int   s3 = __shfl_sync(hmask, sreg,  j + 3, 16);
            float o0 = __shfl_sync(hmask, snorm, j + 0, 16);
            float o1 = __shfl_sync(hmask, snorm, j + 1, 16);
            float o2 = __shfl_sync(hmask, snorm, j + 2, 16);
            float o3 = __shfl_sync(hmask, snorm, j + 3, 16);
            float4 v0 = reinterpret_cast<const float4*>(g_h1)[s0 * 16 + hl];
            float4 v1 = reinterpret_cast<const float4*>(g_h1)[s1 * 16 + hl];
            float4 v2 = reinterpret_cast<const float4*>(g_h1)[s2 * 16 + hl];
            float4 v3 = reinterpret_cast<const float4*>(g_h1)[s3 * 16 + hl];
            a0.x = fmaf(v0.x, o0, a0.x); a0.y = fmaf(v0.y, o0, a0.y);
            a0.z = fmaf(v0.z, o0, a0.z); a0.w = fmaf(v0.w, o0, a0.w);
            a1.x = fmaf(v1.x, o1, a1.x); a1.y = fmaf(v1.y, o1, a1.y);
            a1.z = fmaf(v1.z, o1, a1.z); a1.w = fmaf(v1.w, o1, a1.w);
            a2.x = fmaf(v2.x, o2, a2.x); a2.y = fmaf(v2.y, o2, a2.y);
            a2.z = fmaf(v2.z, o2, a2.z); a2.w = fmaf(v2.w, o2, a2.w);
            a3.x = fmaf(v3.x, o3, a3.x); a3.y = fmaf(v3.y, o3, a3.y);
            a3.w = fmaf(v3.w, o3, a3.w); a3.z = fmaf(v3.z, o3, a3.z);
        }
        for (; j < n; j++) {
            int   s = __shfl_sync(hmask, sreg,  j, 16);
            float o = __shfl_sync(hmask, snorm, j, 16);
            float4 v = reinterpret_cast<const float4*>(g_h1)[s * 16 + hl];
            a0.x = fmaf(v.x, o, a0.x); a0.y = fmaf(v.y, o, a0.y);
            a0.z = fmaf(v.z, o, a0.z); a0.w = fmaf(v.w, o, a0.w);
        }
    }
    float4 r;
    r.x = (a0.x + a1.x) + (a2.x + a3.x);
    r.y = (a0.y + a1.y) + (a2.y + a3.y);
    r.z = (a0.z + a1.z) + (a2.z + a3.z);
    r.w = (a0.w + a1.w) + (a2.w + a3.w);
    reinterpret_cast<float4*>(g_agg1)[node * 16 + hl] = r;
}

// ---- Fused layer-1 epilogue + GEMM2 (64 -> 32) ----
__global__ __launch_bounds__(256) void k_gemm2(const float* __restrict__ W2,
                                               const float* __restrict__ b1) {
    __shared__ float Ws[64 * 32];
    __shared__ float xs[64][68];
    int tid = threadIdx.x;
    int nb  = blockIdx.x * 64;

    #pragma unroll
    for (int r = 0; r < 2; r++) {
        int idx = tid + r * 256;
        reinterpret_cast<float4*>(Ws)[idx] =
            reinterpret_cast<const float4*>(W2)[idx];
    }
    #pragma unroll
    for (int r = 0; r < 4; r++) {
        int idx = tid + r * 256;
        int n = idx >> 4, k4 = idx & 15;
        int node = nb + n;
        float4 v = make_float4(0.f, 0.f, 0.f, 0.f);
        if (node < NN) {
            v = reinterpret_cast<const float4*>(g_agg1)[node * 16 + k4];
            float in_n = g_innorm[node];
            float on   = g_outnorm[node];
            float4 bb  = reinterpret_cast<const float4*>(b1)[k4];
            v.x = fmaxf(fmaf(v.x, in_n, bb.x), 0.f) * on;
            v.y = fmaxf(fmaf(v.y, in_n, bb.y), 0.f) * on;
            v.z = fmaxf(fmaf(v.z, in_n, bb.z), 0.f) * on;
            v.w = fmaxf(fmaf(v.w, in_n, bb.w), 0.f) * on;
        }
        xs[k4 * 4 + 0][n] = v.x;
        xs[k4 * 4 + 1][n] = v.y;
        xs[k4 * 4 + 2][n] = v.z;
        xs[k4 * 4 + 3][n] = v.w;
    }
    __syncthreads();

    int tx = tid & 7;
    int ty = tid >> 3;
    float acc[2][4] = {};
    #pragma unroll
    for (int k = 0; k < 64; k++) {
        float4 wv = *reinterpret_cast<const float4*>(&Ws[k * 32 + tx * 4]);
        float x0 = xs[k][ty * 2 + 0];
        float x1 = xs[k][ty * 2 + 1];
        acc[0][0] += x0 * wv.x; acc[0][1] += x0 * wv.y;
        acc[0][2] += x0 * wv.z; acc[0][3] += x0 * wv.w;
        acc[1][0] += x1 * wv.x; acc[1][1] += x1 * wv.y;
        acc[1][2] += x1 * wv.z; acc[1][3] += x1 * wv.w;
    }
    #pragma unroll
    for (int i = 0; i < 2; i++) {
        int node = nb + ty * 2 + i;
        if (node < NN) {
            float4 o = make_float4(acc[i][0], acc[i][1], acc[i][2], acc[i][3]);
            reinterpret_cast<float4*>(g_h2)[node * 8 + tx] = o;
        }
    }
}

// ---- gather2 + final epilogue. Quarter-warp per node, float4. ----
__global__ __launch_bounds__(256) void k_gather2(const float* __restrict__ b2,
                                                 float* __restrict__ out) {
    int gw = (blockIdx.x * 256 + threadIdx.x) >> 5;
    int lane = threadIdx.x & 31;
    int q = lane >> 3, ql = lane & 7;
    int node = gw * 4 + q;
    if (node >= NN) return;
    unsigned qmask = 0xFFu << (q * 8);
    int beg = g_rowptr[node], end = g_rowptr[node + 1];

    float4 a0 = make_float4(0.f,0.f,0.f,0.f), a1 = a0, a2 = a0, a3 = a0;
    for (int c = beg; c < end; c += 8) {
        int idx = c + ql;
        int sreg = (idx < end) ? g_csr_src[idx] : 0;
        int n = end - c; if (n > 8) n = 8;
        int j = 0;
        for (; j + 4 <= n; j += 4) {
            int s0 = __shfl_sync(qmask, sreg, j + 0, 8);
            int s1 = __shfl_sync(qmask, sreg, j + 1, 8);
            int s2 = __shfl_sync(qmask, sreg, j + 2, 8);
            int s3 = __shfl_sync(qmask, sreg, j + 3, 8);
            float4 v0 = reinterpret_cast<const float4*>(g_h2)[s0 * 8 + ql];
            float4 v1 = reinterpret_cast<const float4*>(g_h2)[s1 * 8 + ql];
            float4 v2 = reinterpret_cast<const float4*>(g_h2)[s2 * 8 + ql];
            float4 v3 = reinterpret_cast<const float4*>(g_h2)[s3 * 8 + ql];
            a0.x += v0.x; a0.y += v0.y; a0.z += v0.z; a0.w += v0.w;
            a1.x += v1.x; a1.y += v1.y; a1.z += v1.z; a1.w += v1.w;
            a2.x += v2.x; a2.y += v2.y; a2.z += v2.z; a2.w += v2.w;
            a3.x += v3.x; a3.y += v3.y; a3.z += v3.z; a3.w += v3.w;
        }
        for (; j < n; j++) {
            int s = __shfl_sync(qmask, sreg, j, 8);
            float4 v = reinterpret_cast<const float4*>(g_h2)[s * 8 + ql];
            a0.x += v.x; a0.y += v.y; a0.z += v.z; a0.w += v.w;
        }
    }
    float4 r;
    r.x = (a0.x + a1.x) + (a2.x + a3.x);
    r.y = (a0.y + a1.y) + (a2.y + a3.y);
    r.z = (a0.z + a1.z) + (a2.z + a3.z);
    r.w = (a0.w + a1.w) + (a2.w + a3.w);
    float inr = g_innorm[node];
    float4 bb = reinterpret_cast<const float4*>(b2)[ql];
    float4 o;
    o.x = fmaf(r.x, inr, bb.x);
    o.y = fmaf(r.y, inr, bb.y);
    o.z = fmaf(r.z, inr, bb.z);
    o.w = fmaf(r.w, inr, bb.w);
    reinterpret_cast<float4*>(out)[node * 8 + ql] = o;
}

extern "C" void kernel_launch(void* const* d_in, const int* in_sizes, int n_in,
                              void* d_out, int out_size) {
    const float* x   = (const float*)d_in[0];
    const int*   src = (const int*)  d_in[1];
    const int*   dst = (const int*)  d_in[2];
    const float* W1  = (const float*)d_in[3];
    const float* b1  = (const float*)d_in[4];
    const float* W2  = (const float*)d_in[5];
    const float* b2  = (const float*)d_in[6];
    float* out = (float*)d_out;

    const int T = 256;

    // Fork a side stream for GEMM1 (depends only on x, W1) so it overlaps the
    // CSR build chain. Capture-safe event fork/join; sequential fallback.
    cudaStream_t s2 = 0;
    cudaEvent_t evA = 0, evB = 0;
    bool forked =
        (cudaStreamCreateWithFlags(&s2, cudaStreamNonBlocking) == cudaSuccess) &&
        (cudaEventCreateWithFlags(&evA, cudaEventDisableTiming) == cudaSuccess) &&
        (cudaEventCreateWithFlags(&evB, cudaEventDisableTiming) == cudaSuccess) &&
        (cudaEventRecord(evA, 0) == cudaSuccess) &&
        (cudaStreamWaitEvent(s2, evA, 0) == cudaSuccess);

    if (forked)
        k_gemm1<<<(NN + 63) / 64, 256, 0, s2>>>(x, W1);

    k_zero     <<<(NN + T - 1) / T, T>>>();
    k_deg      <<<(NE + T - 1) / T, T>>>(src, dst);
    k_scan1    <<<SCAN_NBLK, 256>>>();
    k_scan2    <<<1, 128>>>();
    k_scan3norm<<<(NN + T - 1) / T, T>>>();
    k_bucket   <<<(NE + T - 1) / T, T>>>(src, dst);

    if (forked) {
        cudaEventRecord(evB, s2);
        cudaStreamWaitEvent(0, evB, 0);
    } else {
        k_gemm1<<<(NN + 63) / 64, 256>>>(x, W1);
    }

    k_gather1<<<(NN / 2 * 32) / 256, 256>>>();          // 6250 blocks
    k_gemm2  <<<(NN + 63) / 64, 256>>>(W2, b1);
    k_gather2<<<(NN / 4 * 32) / 256, 256>>>(b2, out);   // 3125 blocks
}